// round 7
// baseline (speedup 1.0000x reference)
#include <cuda_runtime.h>
#include <cstdint>

#define Dz 64
#define Hh 128
#define Wf 128               // floats per row
#define ROWS 8               // compute warps per block = rows per tile
#define NWARPS 9             // 8 compute + 1 producer
#define NS 4                 // pipeline stages
#define DSPLIT 8
#define DCHUNK (Dz / DSPLIT) // 8
#define VOLS 32              // B*C
#define NB ((Hh / ROWS) * VOLS * DSPLIT)   // 4096 blocks
#define ROWBYTES (Wf * 4)          // 512
#define TILEROWS (ROWS + 2)        // 10
#define STAGEBYTES (TILEROWS * ROWBYTES)   // 5120 per tensor
#define PLANEF (Hh * Wf)           // 16384 floats per plane
#define DYN_STAGE0 1024
#define DYN_TOTAL (DYN_STAGE0 + NS * 2 * STAGEBYTES)   // 41984

#define NEG1 0xBF800000BF800000ULL   // (-1.f, -1.f) packed

__device__ float g_partial[NB];
__device__ unsigned int g_count;

struct U2 { unsigned long long a, b; };

__device__ __forceinline__ unsigned long long fma2(unsigned long long a,
                                                   unsigned long long b,
                                                   unsigned long long c) {
    unsigned long long d;
    asm("fma.rn.f32x2 %0, %1, %2, %3;" : "=l"(d) : "l"(a), "l"(b), "l"(c));
    return d;
}
__device__ __forceinline__ unsigned long long add2(unsigned long long a,
                                                   unsigned long long b) {
    unsigned long long d;
    asm("add.rn.f32x2 %0, %1, %2;" : "=l"(d) : "l"(a), "l"(b));
    return d;
}
__device__ __forceinline__ float lo32(unsigned long long v) { return __uint_as_float((unsigned)v); }
__device__ __forceinline__ float hi32(unsigned long long v) { return __uint_as_float((unsigned)(v >> 32)); }

__device__ __forceinline__ uint32_t smem_u32(const void* p) {
    uint32_t a;
    asm("{ .reg .u64 t; cvta.to.shared.u64 t, %1; cvt.u32.u64 %0, t; }" : "=r"(a) : "l"(p));
    return a;
}
__device__ __forceinline__ void mbar_init(uint32_t a, uint32_t cnt) {
    asm volatile("mbarrier.init.shared.b64 [%0], %1;" :: "r"(a), "r"(cnt) : "memory");
}
__device__ __forceinline__ void mbar_expect_tx(uint32_t a, uint32_t bytes) {
    asm volatile("mbarrier.arrive.expect_tx.shared.b64 _, [%0], %1;" :: "r"(a), "r"(bytes) : "memory");
}
__device__ __forceinline__ void mbar_arrive(uint32_t a) {
    asm volatile("mbarrier.arrive.shared.b64 _, [%0];" :: "r"(a) : "memory");
}
__device__ __forceinline__ void mbar_wait(uint32_t a, uint32_t parity) {
    uint32_t done;
    asm volatile("{\n\t.reg .pred p;\n\t"
                 "mbarrier.try_wait.parity.acquire.cta.shared::cta.b64 p, [%1], %2;\n\t"
                 "selp.b32 %0, 1, 0, p;\n\t}"
                 : "=r"(done) : "r"(a), "r"(parity) : "memory");
    if (!done) {
        asm volatile("{\n\t.reg .pred P1;\n\t"
                     "W_%=:\n\t"
                     "mbarrier.try_wait.parity.acquire.cta.shared::cta.b64 P1, [%0], %1, 0x989680;\n\t"
                     "@P1 bra.uni D_%=;\n\t"
                     "bra.uni W_%=;\n\t"
                     "D_%=:\n\t}"
                     :: "r"(a), "r"(parity) : "memory");
    }
}
__device__ __forceinline__ void bulk_g2s(uint32_t dst, const void* src, uint32_t bytes, uint32_t mbar) {
    asm volatile("cp.async.bulk.shared::cta.global.mbarrier::complete_tx::bytes [%0], [%1], %2, [%3];"
                 :: "r"(dst), "l"(src), "r"(bytes), "r"(mbar) : "memory");
}

__global__ __launch_bounds__(NWARPS * 32, 4)
void gradloss_kernel(const float* __restrict__ xf, const float* __restrict__ tf,
                     float* __restrict__ out)
{
    extern __shared__ char dynsm[];
    const uint32_t smb = smem_u32(dynsm);
    __shared__ float wsum[ROWS];
    __shared__ int   isLast;

    const int tid  = threadIdx.x;
    const int lane = tid & 31;
    const int warp = tid >> 5;
    const int h0   = blockIdx.x * ROWS;
    const int v    = blockIdx.y;
    const int d0   = blockIdx.z * DCHUNK;

    int hStart = h0 - 1;
    if (hStart < 0) hStart = 0;
    if (hStart > Hh - TILEROWS) hStart = Hh - TILEROWS;

    const float* xsrc0 = xf + (size_t)v * Dz * PLANEF + (size_t)d0 * PLANEF + (size_t)hStart * Wf;
    const float* tsrc0 = tf + (size_t)v * Dz * PLANEF + (size_t)d0 * PLANEF + (size_t)hStart * Wf;

    #define FULLB(s)  (smb + (uint32_t)(s) * 16u)
    #define EMPTYB(s) (smb + (uint32_t)(s) * 16u + 8u)
    #define XS(s)     ((const ulonglong2*)(dynsm + DYN_STAGE0 + (s) * (2 * STAGEBYTES)))
    #define TS(s)     ((const ulonglong2*)(dynsm + DYN_STAGE0 + (s) * (2 * STAGEBYTES) + STAGEBYTES))
    #define XADDR(s)  (smb + DYN_STAGE0 + (uint32_t)(s) * (2 * STAGEBYTES))
    #define TADDR(s)  (smb + DYN_STAGE0 + (uint32_t)(s) * (2 * STAGEBYTES) + STAGEBYTES)

    if (tid == 0) {
        #pragma unroll
        for (int s = 0; s < NS; ++s) { mbar_init(FULLB(s), 1); mbar_init(EMPTYB(s), ROWS); }
    }
    __syncthreads();

    float acc = 0.0f;

    if (warp == ROWS) {
        // ================= producer warp (thread lane 0 only) =================
        if (lane == 0) {
            #pragma unroll 1
            for (int ai = 0; ai < DCHUNK; ++ai) {
                const int s = ai & 3;
                const int k = ai >> 2;
                if (ai >= NS) mbar_wait(EMPTYB(s), (k - 1) & 1);
                mbar_expect_tx(FULLB(s), 2u * STAGEBYTES);
                const size_t off = (size_t)ai * PLANEF;
                bulk_g2s(XADDR(s), xsrc0 + off, STAGEBYTES, FULLB(s));
                bulk_g2s(TADDR(s), tsrc0 + off, STAGEBYTES, FULLB(s));
            }
        }
    } else {
        // ================= compute warps (0..7) =================
        const int gh  = h0 + warp;
        const int lc  = gh - hStart;
        const int lcm = (gh == 0)      ? lc : lc - 1;   // clamped => branch-free H edges
        const int lcp = (gh == Hh - 1) ? lc : lc + 1;
        const int lcOff = lc  * 32 + lane;   // ulonglong2 units
        const int hmOff = lcm * 32 + lane;
        const int hpOff = lcp * 32 + lane;

        // boundary centers via plain LDG (1 row each; adjacent chunk's bulk data -> L2 hit)
        U2 u_bnd; u_bnd.a = 0; u_bnd.b = 0;
        if (d0 > 0) {
            const ulonglong2* xb = (const ulonglong2*)(xf + (size_t)v * Dz * PLANEF
                                   + (size_t)(d0 - 1) * PLANEF + (size_t)gh * Wf);
            const ulonglong2* tb = (const ulonglong2*)(tf + (size_t)v * Dz * PLANEF
                                   + (size_t)(d0 - 1) * PLANEF + (size_t)gh * Wf);
            ulonglong2 xr = xb[lane], tr = tb[lane];
            u_bnd.a = fma2(tr.x, NEG1, xr.x); u_bnd.b = fma2(tr.y, NEG1, xr.y);
        }
        U2 u_nxt; u_nxt.a = 0; u_nxt.b = 0;
        if (d0 + DCHUNK < Dz) {
            const ulonglong2* xb = (const ulonglong2*)(xf + (size_t)v * Dz * PLANEF
                                   + (size_t)(d0 + DCHUNK) * PLANEF + (size_t)gh * Wf);
            const ulonglong2* tb = (const ulonglong2*)(tf + (size_t)v * Dz * PLANEF
                                   + (size_t)(d0 + DCHUNK) * PLANEF + (size_t)gh * Wf);
            ulonglong2 xr = xb[lane], tr = tb[lane];
            u_nxt.a = fma2(tr.x, NEG1, xr.x); u_nxt.b = fma2(tr.y, NEG1, xr.y);
        }

        U2 u_m, u_c, u_p;
        u_m.a = u_m.b = 0; u_c.a = u_c.b = 0;
        u_p = u_bnd;

        unsigned long long acc2D = 0, acc2H = 0;
        float accWx = 0.f, accWm = 0.f, accWw = 0.f;

        #define FOLD_CENTER(S)                                                   \
            ulonglong2 xc_ = XS(S)[lcOff], tc_ = TS(S)[lcOff];                   \
            U2 unew_; unew_.a = fma2(tc_.x, NEG1, xc_.x);                        \
            unew_.b = fma2(tc_.y, NEG1, xc_.y);                                  \
            u_m = u_c; u_c = u_p; u_p = unew_;

        #define D_INT() do {                                                     \
            unsigned long long da_ = fma2(u_m.a, NEG1, u_p.a);                   \
            unsigned long long db_ = fma2(u_m.b, NEG1, u_p.b);                   \
            acc2D = fma2(da_, da_, acc2D); acc2D = fma2(db_, db_, acc2D);        \
        } while (0)

        #define D_EDGE(HI, LO) do {                                              \
            unsigned long long da_ = fma2((LO).a, NEG1, (HI).a); da_ = add2(da_, da_); \
            unsigned long long db_ = fma2((LO).b, NEG1, (HI).b); db_ = add2(db_, db_); \
            acc2D = fma2(da_, da_, acc2D); acc2D = fma2(db_, db_, acc2D);        \
        } while (0)

        #define HW(SQ, CEN) do {                                                 \
            ulonglong2 xp_ = XS(SQ)[hpOff], tp_ = TS(SQ)[hpOff];                 \
            ulonglong2 xm_ = XS(SQ)[hmOff], tm_ = TS(SQ)[hmOff];                 \
            unsigned long long hpa = fma2(tp_.x, NEG1, xp_.x);                   \
            unsigned long long hpb = fma2(tp_.y, NEG1, xp_.y);                   \
            unsigned long long hma = fma2(tm_.x, NEG1, xm_.x);                   \
            unsigned long long hmb = fma2(tm_.y, NEG1, xm_.y);                   \
            unsigned long long dha = fma2(hma, NEG1, hpa);                       \
            unsigned long long dhb = fma2(hmb, NEG1, hpb);                       \
            acc2H = fma2(dha, dha, acc2H); acc2H = fma2(dhb, dhb, acc2H);        \
            float f0 = lo32((CEN).a), f1 = hi32((CEN).a);                        \
            float f2 = lo32((CEN).b), f3 = hi32((CEN).b);                        \
            float wl = __shfl_up_sync(0xffffffffu, f3, 1);                       \
            float wr = __shfl_down_sync(0xffffffffu, f0, 1);                     \
            float ax = (lane == 0)  ? f0 : wl;                                   \
            float aw = (lane == 31) ? f3 : wr;                                   \
            float dx = f1 - ax, dy = f2 - f0, dz = f3 - f1, dw = aw - f2;        \
            accWx = fmaf(dx, dx, accWx); accWm = fmaf(dy, dy, accWm);            \
            accWm = fmaf(dz, dz, accWm); accWw = fmaf(dw, dw, accWw);            \
        } while (0)

        #define RELEASE(SP) do {                                                 \
            __syncwarp();                                                        \
            if (lane == 0) mbar_arrive(EMPTYB(SP));                              \
        } while (0)

        // ---- peeled group (ai = 0..3) ----
        {   mbar_wait(FULLB(0), 0); FOLD_CENTER(0); }                 // ai=0
        {   mbar_wait(FULLB(1), 0); FOLD_CENTER(1);                   // ai=1
            if (d0 == 0) D_EDGE(u_p, u_c); else D_INT();
            HW(0, u_c); RELEASE(0); }
        {   mbar_wait(FULLB(2), 0); FOLD_CENTER(2);                   // ai=2
            D_INT(); HW(1, u_c); RELEASE(1); }
        {   mbar_wait(FULLB(3), 0); FOLD_CENTER(3);                   // ai=3
            D_INT(); HW(2, u_c); RELEASE(2); }

        // ---- main: it = 1..DCHUNK/4-1 (ai = 4..DCHUNK-1) ----
        #pragma unroll 1
        for (int it = 1; it < DCHUNK / 4; ++it) {
            const uint32_t fp = it & 1;
            {   mbar_wait(FULLB(0), fp); FOLD_CENTER(0);
                D_INT(); HW(3, u_c); RELEASE(3); }
            {   mbar_wait(FULLB(1), fp); FOLD_CENTER(1);
                D_INT(); HW(0, u_c); RELEASE(0); }
            {   mbar_wait(FULLB(2), fp); FOLD_CENTER(2);
                D_INT(); HW(1, u_c); RELEASE(1); }
            {   mbar_wait(FULLB(3), fp); FOLD_CENTER(3);
                D_INT(); HW(2, u_c); RELEASE(2); }
        }

        // ---- tail: plane d0+DCHUNK-1 (center u_p, halos in stage 3 — never released) ----
        if (d0 + DCHUNK == Dz) {
            D_EDGE(u_p, u_c);
        } else {
            unsigned long long da_ = fma2(u_c.a, NEG1, u_nxt.a);
            unsigned long long db_ = fma2(u_c.b, NEG1, u_nxt.b);
            acc2D = fma2(da_, da_, acc2D); acc2D = fma2(db_, db_, acc2D);
        }
        HW(3, u_p);

        // ---- hoisted scales ----
        const float sH2 = (gh == 0 || gh == Hh - 1) ? 1.0f : 0.25f;
        const float sx2 = (lane == 0)  ? 1.0f : 0.25f;
        const float sw2 = (lane == 31) ? 1.0f : 0.25f;
        acc = 0.25f * (lo32(acc2D) + hi32(acc2D))
            + sH2   * (lo32(acc2H) + hi32(acc2H))
            + 0.25f * accWm + sx2 * accWx + sw2 * accWw;
    }

    // ================= block reduction (all 9 warps) =================
    #pragma unroll
    for (int off = 16; off > 0; off >>= 1)
        acc += __shfl_down_sync(0xffffffffu, acc, off);
    if (warp < ROWS && lane == 0) wsum[warp] = acc;
    __syncthreads();
    if (tid == 0) {
        float s = 0.0f;
        #pragma unroll
        for (int i = 0; i < ROWS; ++i) s += wsum[i];
        const int bid = blockIdx.x + gridDim.x * (blockIdx.y + gridDim.y * blockIdx.z);
        g_partial[bid] = s;
        __threadfence();
        unsigned old = atomicAdd(&g_count, 1u);
        isLast = (old == NB - 1) ? 1 : 0;
    }
    __syncthreads();

    if (isLast) {
        __threadfence();
        const volatile float* gp = g_partial;
        double sd = 0.0;
        for (int i = tid; i < NB; i += NWARPS * 32) sd += (double)gp[i];
        #pragma unroll
        for (int off = 16; off > 0; off >>= 1)
            sd += __shfl_down_sync(0xffffffffu, sd, off);
        __shared__ double dsum[NWARPS];
        if (lane == 0) dsum[warp] = sd;
        __syncthreads();
        if (tid == 0) {
            double tot = 0.0;
            #pragma unroll
            for (int i = 0; i < NWARPS; ++i) tot += dsum[i];
            out[0] = (float)(tot * (1.0 / 8388608.0));
            g_count = 0;
        }
    }
}

extern "C" void kernel_launch(void* const* d_in, const int* in_sizes, int n_in,
                              void* d_out, int out_size)
{
    const float* x = (const float*)d_in[0];
    const float* t = (const float*)d_in[1];

    cudaFuncSetAttribute(gradloss_kernel,
                         cudaFuncAttributeMaxDynamicSharedMemorySize, DYN_TOTAL);

    dim3 grid(Hh / ROWS, VOLS, DSPLIT);   // 16 x 32 x 8 = 4096 blocks
    gradloss_kernel<<<grid, NWARPS * 32, DYN_TOTAL>>>(x, t, (float*)d_out);
}

// round 8
// speedup vs baseline: 1.2950x; 1.2950x over previous
#include <cuda_runtime.h>
#include <cstdint>

#define Dz 64
#define Hh 128
#define Wf 128               // floats per row
#define ROWS 8               // compute warps per block = rows per tile
#define NWARPS 9             // 8 compute + 1 producer
#define NS 4                 // pipeline stages
#define VOLS 32              // B*C
#define NB ((Hh / ROWS) * VOLS)    // 512 blocks — single wave
#define ROWBYTES (Wf * 4)          // 512
#define TILEROWS (ROWS + 2)        // 10
#define STAGEBYTES (TILEROWS * ROWBYTES)   // 5120 per tensor
#define PLANEF (Hh * Wf)           // 16384 floats per plane
#define DYN_STAGE0 1024
#define DYN_TOTAL (DYN_STAGE0 + NS * 2 * STAGEBYTES)   // 41984

#define NEG1 0xBF800000BF800000ULL   // (-1.f, -1.f) packed

__device__ float g_partial[NB];
__device__ unsigned int g_count;

struct U2 { unsigned long long a, b; };

__device__ __forceinline__ unsigned long long fma2(unsigned long long a,
                                                   unsigned long long b,
                                                   unsigned long long c) {
    unsigned long long d;
    asm("fma.rn.f32x2 %0, %1, %2, %3;" : "=l"(d) : "l"(a), "l"(b), "l"(c));
    return d;
}
__device__ __forceinline__ unsigned long long add2(unsigned long long a,
                                                   unsigned long long b) {
    unsigned long long d;
    asm("add.rn.f32x2 %0, %1, %2;" : "=l"(d) : "l"(a), "l"(b));
    return d;
}
__device__ __forceinline__ float lo32(unsigned long long v) { return __uint_as_float((unsigned)v); }
__device__ __forceinline__ float hi32(unsigned long long v) { return __uint_as_float((unsigned)(v >> 32)); }

__device__ __forceinline__ uint32_t smem_u32(const void* p) {
    uint32_t a;
    asm("{ .reg .u64 t; cvta.to.shared.u64 t, %1; cvt.u32.u64 %0, t; }" : "=r"(a) : "l"(p));
    return a;
}
__device__ __forceinline__ void mbar_init(uint32_t a, uint32_t cnt) {
    asm volatile("mbarrier.init.shared.b64 [%0], %1;" :: "r"(a), "r"(cnt) : "memory");
}
__device__ __forceinline__ void mbar_expect_tx(uint32_t a, uint32_t bytes) {
    asm volatile("mbarrier.arrive.expect_tx.shared.b64 _, [%0], %1;" :: "r"(a), "r"(bytes) : "memory");
}
__device__ __forceinline__ void mbar_arrive(uint32_t a) {
    asm volatile("mbarrier.arrive.shared.b64 _, [%0];" :: "r"(a) : "memory");
}
__device__ __forceinline__ void mbar_wait(uint32_t a, uint32_t parity) {
    uint32_t done;
    asm volatile("{\n\t.reg .pred p;\n\t"
                 "mbarrier.try_wait.parity.acquire.cta.shared::cta.b64 p, [%1], %2;\n\t"
                 "selp.b32 %0, 1, 0, p;\n\t}"
                 : "=r"(done) : "r"(a), "r"(parity) : "memory");
    if (!done) {
        asm volatile("{\n\t.reg .pred P1;\n\t"
                     "W_%=:\n\t"
                     "mbarrier.try_wait.parity.acquire.cta.shared::cta.b64 P1, [%0], %1, 0x989680;\n\t"
                     "@P1 bra.uni D_%=;\n\t"
                     "bra.uni W_%=;\n\t"
                     "D_%=:\n\t}"
                     :: "r"(a), "r"(parity) : "memory");
    }
}
__device__ __forceinline__ void bulk_g2s(uint32_t dst, const void* src, uint32_t bytes, uint32_t mbar) {
    asm volatile("cp.async.bulk.shared::cta.global.mbarrier::complete_tx::bytes [%0], [%1], %2, [%3];"
                 :: "r"(dst), "l"(src), "r"(bytes), "r"(mbar) : "memory");
}

__global__ __launch_bounds__(NWARPS * 32, 4)
void gradloss_kernel(const float* __restrict__ xf, const float* __restrict__ tf,
                     float* __restrict__ out)
{
    extern __shared__ char dynsm[];
    const uint32_t smb = smem_u32(dynsm);
    __shared__ float wsum[ROWS];
    __shared__ int   isLast;

    const int tid  = threadIdx.x;
    const int lane = tid & 31;
    const int warp = tid >> 5;
    const int h0   = blockIdx.x * ROWS;
    const int v    = blockIdx.y;

    int hStart = h0 - 1;
    if (hStart < 0) hStart = 0;
    if (hStart > Hh - TILEROWS) hStart = Hh - TILEROWS;

    const float* xsrc0 = xf + (size_t)v * Dz * PLANEF + (size_t)hStart * Wf;
    const float* tsrc0 = tf + (size_t)v * Dz * PLANEF + (size_t)hStart * Wf;

    #define FULLB(s)  (smb + (uint32_t)(s) * 16u)
    #define EMPTYB(s) (smb + (uint32_t)(s) * 16u + 8u)
    #define XS(s)     ((const ulonglong2*)(dynsm + DYN_STAGE0 + (s) * (2 * STAGEBYTES)))
    #define TS(s)     ((const ulonglong2*)(dynsm + DYN_STAGE0 + (s) * (2 * STAGEBYTES) + STAGEBYTES))
    #define XADDR(s)  (smb + DYN_STAGE0 + (uint32_t)(s) * (2 * STAGEBYTES))
    #define TADDR(s)  (smb + DYN_STAGE0 + (uint32_t)(s) * (2 * STAGEBYTES) + STAGEBYTES)

    if (tid == 0) {
        #pragma unroll
        for (int s = 0; s < NS; ++s) { mbar_init(FULLB(s), 1); mbar_init(EMPTYB(s), ROWS); }
    }
    __syncthreads();

    float acc = 0.0f;

    if (warp == ROWS) {
        // ================= producer warp (lane 0 only) =================
        if (lane == 0) {
            #pragma unroll 1
            for (int ai = 0; ai < Dz; ++ai) {
                const int s = ai & 3;
                const int k = ai >> 2;
                if (ai >= NS) mbar_wait(EMPTYB(s), (k - 1) & 1);
                mbar_expect_tx(FULLB(s), 2u * STAGEBYTES);
                const size_t off = (size_t)ai * PLANEF;
                bulk_g2s(XADDR(s), xsrc0 + off, STAGEBYTES, FULLB(s));
                bulk_g2s(TADDR(s), tsrc0 + off, STAGEBYTES, FULLB(s));
            }
        }
    } else {
        // ================= compute warps (0..7) =================
        const int gh  = h0 + warp;
        const int lc  = gh - hStart;
        const int lcm = (gh == 0)      ? lc : lc - 1;   // clamped => branch-free H edges
        const int lcp = (gh == Hh - 1) ? lc : lc + 1;
        const int lcOff = lc  * 32 + lane;   // ulonglong2 units
        const int hmOff = lcm * 32 + lane;
        const int hpOff = lcp * 32 + lane;

        U2 u_m, u_c, u_p;
        u_m.a = u_m.b = 0; u_c.a = u_c.b = 0; u_p.a = u_p.b = 0;

        unsigned long long acc2D = 0, acc2H = 0;
        float accWx = 0.f, accWm = 0.f, accWw = 0.f;

        #define FOLD_CENTER(S)                                                   \
            ulonglong2 xc_ = XS(S)[lcOff], tc_ = TS(S)[lcOff];                   \
            U2 unew_; unew_.a = fma2(tc_.x, NEG1, xc_.x);                        \
            unew_.b = fma2(tc_.y, NEG1, xc_.y);                                  \
            u_m = u_c; u_c = u_p; u_p = unew_;

        #define D_INT() do {                                                     \
            unsigned long long da_ = fma2(u_m.a, NEG1, u_p.a);                   \
            unsigned long long db_ = fma2(u_m.b, NEG1, u_p.b);                   \
            acc2D = fma2(da_, da_, acc2D); acc2D = fma2(db_, db_, acc2D);        \
        } while (0)

        #define D_EDGE(HI, LO) do {                                              \
            unsigned long long da_ = fma2((LO).a, NEG1, (HI).a); da_ = add2(da_, da_); \
            unsigned long long db_ = fma2((LO).b, NEG1, (HI).b); db_ = add2(db_, db_); \
            acc2D = fma2(da_, da_, acc2D); acc2D = fma2(db_, db_, acc2D);        \
        } while (0)

        #define HW(SQ, CEN) do {                                                 \
            ulonglong2 xp_ = XS(SQ)[hpOff], tp_ = TS(SQ)[hpOff];                 \
            ulonglong2 xm_ = XS(SQ)[hmOff], tm_ = TS(SQ)[hmOff];                 \
            unsigned long long hpa = fma2(tp_.x, NEG1, xp_.x);                   \
            unsigned long long hpb = fma2(tp_.y, NEG1, xp_.y);                   \
            unsigned long long hma = fma2(tm_.x, NEG1, xm_.x);                   \
            unsigned long long hmb = fma2(tm_.y, NEG1, xm_.y);                   \
            unsigned long long dha = fma2(hma, NEG1, hpa);                       \
            unsigned long long dhb = fma2(hmb, NEG1, hpb);                       \
            acc2H = fma2(dha, dha, acc2H); acc2H = fma2(dhb, dhb, acc2H);        \
            float f0 = lo32((CEN).a), f1 = hi32((CEN).a);                        \
            float f2 = lo32((CEN).b), f3 = hi32((CEN).b);                        \
            float wl = __shfl_up_sync(0xffffffffu, f3, 1);                       \
            float wr = __shfl_down_sync(0xffffffffu, f0, 1);                     \
            float ax = (lane == 0)  ? f0 : wl;                                   \
            float aw = (lane == 31) ? f3 : wr;                                   \
            float dx = f1 - ax, dy = f2 - f0, dz = f3 - f1, dw = aw - f2;        \
            accWx = fmaf(dx, dx, accWx); accWm = fmaf(dy, dy, accWm);            \
            accWm = fmaf(dz, dz, accWm); accWw = fmaf(dw, dw, accWw);            \
        } while (0)

        #define RELEASE(SP) do {                                                 \
            __syncwarp();                                                        \
            if (lane == 0) mbar_arrive(EMPTYB(SP));                              \
        } while (0)

        // ---- peeled group (ai = 0..3) ----
        {   mbar_wait(FULLB(0), 0); FOLD_CENTER(0); }                 // ai=0
        {   mbar_wait(FULLB(1), 0); FOLD_CENTER(1);                   // ai=1: plane 0
            D_EDGE(u_p, u_c);
            HW(0, u_c); RELEASE(0); }
        {   mbar_wait(FULLB(2), 0); FOLD_CENTER(2);                   // ai=2
            D_INT(); HW(1, u_c); RELEASE(1); }
        {   mbar_wait(FULLB(3), 0); FOLD_CENTER(3);                   // ai=3
            D_INT(); HW(2, u_c); RELEASE(2); }

        // ---- main: it = 1..15 (ai = 4..63) ----
        #pragma unroll 1
        for (int it = 1; it < Dz / 4; ++it) {
            const uint32_t fp = it & 1;
            {   mbar_wait(FULLB(0), fp); FOLD_CENTER(0);
                D_INT(); HW(3, u_c); RELEASE(3); }
            {   mbar_wait(FULLB(1), fp); FOLD_CENTER(1);
                D_INT(); HW(0, u_c); RELEASE(0); }
            {   mbar_wait(FULLB(2), fp); FOLD_CENTER(2);
                D_INT(); HW(1, u_c); RELEASE(1); }
            {   mbar_wait(FULLB(3), fp); FOLD_CENTER(3);
                D_INT(); HW(2, u_c); RELEASE(2); }
        }

        // ---- tail: plane 63 (center u_p, halos in stage 3 — never released) ----
        D_EDGE(u_p, u_c);
        HW(3, u_p);

        // ---- hoisted scales ----
        const float sH2 = (gh == 0 || gh == Hh - 1) ? 1.0f : 0.25f;
        const float sx2 = (lane == 0)  ? 1.0f : 0.25f;
        const float sw2 = (lane == 31) ? 1.0f : 0.25f;
        acc = 0.25f * (lo32(acc2D) + hi32(acc2D))
            + sH2   * (lo32(acc2H) + hi32(acc2H))
            + 0.25f * accWm + sx2 * accWx + sw2 * accWw;
    }

    // ================= block reduction (all 9 warps) =================
    #pragma unroll
    for (int off = 16; off > 0; off >>= 1)
        acc += __shfl_down_sync(0xffffffffu, acc, off);
    if (warp < ROWS && lane == 0) wsum[warp] = acc;
    __syncthreads();
    if (tid == 0) {
        float s = 0.0f;
        #pragma unroll
        for (int i = 0; i < ROWS; ++i) s += wsum[i];
        const int bid = blockIdx.x + gridDim.x * blockIdx.y;
        g_partial[bid] = s;
        __threadfence();
        unsigned old = atomicAdd(&g_count, 1u);
        isLast = (old == NB - 1) ? 1 : 0;
    }
    __syncthreads();

    if (isLast) {
        __threadfence();
        const volatile float* gp = g_partial;
        double sd = 0.0;
        for (int i = tid; i < NB; i += NWARPS * 32) sd += (double)gp[i];
        #pragma unroll
        for (int off = 16; off > 0; off >>= 1)
            sd += __shfl_down_sync(0xffffffffu, sd, off);
        __shared__ double dsum[NWARPS];
        if (lane == 0) dsum[warp] = sd;
        __syncthreads();
        if (tid == 0) {
            double tot = 0.0;
            #pragma unroll
            for (int i = 0; i < NWARPS; ++i) tot += dsum[i];
            out[0] = (float)(tot * (1.0 / 8388608.0));
            g_count = 0;
        }
    }
}

extern "C" void kernel_launch(void* const* d_in, const int* in_sizes, int n_in,
                              void* d_out, int out_size)
{
    const float* x = (const float*)d_in[0];
    const float* t = (const float*)d_in[1];

    cudaFuncSetAttribute(gradloss_kernel,
                         cudaFuncAttributeMaxDynamicSharedMemorySize, DYN_TOTAL);

    dim3 grid(Hh / ROWS, VOLS);           // 16 x 32 = 512 blocks — single wave
    gradloss_kernel<<<grid, NWARPS * 32, DYN_TOTAL>>>(x, t, (float*)d_out);
}